// round 14
// baseline (speedup 1.0000x reference)
#include <cuda_runtime.h>
#include <math.h>

// ---------------- problem constants ----------------
#define ZD 8
#define HD_ 96
#define WD 192
#define CDIM 192
#define HEADS 6
#define HDIM 32
#define LW 144
#define NWIN 1024          // 4*16*16
#define NPOS 3312
#define WTH 384            // WIN_TYPES*HEADS = 64*6
#define TOKENS 147456      // 8*96*192
#define SCALE_Q 0.17677669529663687f   // 32^-0.5

// ---------------- scratch (device globals; no runtime alloc) ----------------
__device__ float g_buf192[147456*192];      // LN1 out (window layout) / attn out / LN2 out
__device__ float g_qkv  [147456*576];       // qkv window layout
__device__ float g_mlp1 [147456*768];
__device__ float g_xA   [147456*192];
__device__ float g_xB   [147456*192];
__device__ float g_tabT [2*384*3312];       // transposed bias table per depth block

// ---------------- window <-> token index mapping ----------------
// window row r = win*144 + local ; win = (nz*16+nh)*16+nw ; local = (lz*6+lh)*12+lw
// rolled grid coords (zr,hr,wr) = (nz*2+lz, nh*6+lh, nw*12+lw)
// source/dest token = ((zr+1)%8, (hr+3)%96, (wr+6)%192) when roll else (zr,hr,wr)
__device__ __forceinline__ int token_of_winrow(int r, int roll) {
    int win = r / 144, l = r - win * 144;
    int nz = win >> 8;
    int rem = win & 255;
    int nh = rem >> 4, nw = rem & 15;
    int lz = l / 72; int lr = l - lz * 72;
    int lh = lr / 12; int lw = lr - lh * 12;
    int z = nz * 2 + lz, h = nh * 6 + lh, w = nw * 12 + lw;
    if (roll) {
        z = (z + 1) & 7;
        h += 3; if (h >= 96) h -= 96;
        w += 6; if (w >= 192) w -= 192;
    }
    return (z * 96 + h) * 192 + w;
}

// ---------------- LayerNorm (optionally gathering through the window permutation) ----------------
// grid = 147456 blocks (dest row), block = 192 threads
__global__ void ln_kernel(const float* __restrict__ x, const float* __restrict__ g,
                          const float* __restrict__ b, float* __restrict__ out,
                          int gather, int roll)
{
    int r = blockIdx.x;
    int c = threadIdx.x;
    int n = gather ? token_of_winrow(r, roll) : r;
    float v = x[(size_t)n * 192 + c];

    __shared__ float ssum[6], ssq[6];
    float s = v, q = v * v;
    #pragma unroll
    for (int o = 16; o; o >>= 1) {
        s += __shfl_xor_sync(0xffffffffu, s, o);
        q += __shfl_xor_sync(0xffffffffu, q, o);
    }
    int w = c >> 5, l = c & 31;
    if (l == 0) { ssum[w] = s; ssq[w] = q; }
    __syncthreads();
    float ts = 0.f, tq = 0.f;
    #pragma unroll
    for (int i = 0; i < 6; i++) { ts += ssum[i]; tq += ssq[i]; }
    float mean = ts * (1.f / 192.f);
    float var  = tq * (1.f / 192.f) - mean * mean;
    float inv  = rsqrtf(var + 1e-5f);
    out[(size_t)r * 192 + c] = (v - mean) * inv * g[c] + b[c];
}

// ---------------- bias table transpose: tabT[blk][wt*6+h][p] = tab[blk][p][wt*6+h] ----------------
__global__ void bias_transpose_kernel(const float* __restrict__ tab, float* __restrict__ out)
{
    int idx = blockIdx.x * 256 + threadIdx.x;
    const int total = 2 * WTH * NPOS;
    if (idx >= total) return;
    int p = idx % NPOS;
    int rest = idx / NPOS;
    int wth = rest % WTH;
    int blk = rest / WTH;
    out[idx] = tab[((size_t)blk * NPOS + p) * WTH + wth];
}

// ---------------- SGEMM: C = A(MxK) @ B(KxN) + bias, with fused epilogues ----------------
// EPI 0: store   (qkv)
// EPI 1: GELU exact then store (mlp1)
// EPI 2: scatter through inverse window perm + residual (proj), N==192
// EPI 3: residual same-row (mlp2), N==192
template<int EPI>
__global__ void __launch_bounds__(128)
sgemm_kernel(const float* __restrict__ A, const float* __restrict__ Bw,
             const float* __restrict__ bias, float* __restrict__ C,
             const float* __restrict__ res, int N, int K, int roll)
{
    __shared__ float As[16][128];   // transposed A tile
    __shared__ float Bs[16][64];
    const int bm = blockIdx.y * 128;
    const int bn = blockIdx.x * 64;
    const int tid = threadIdx.x;
    const int ty = tid >> 3, tx = tid & 7;

    float acc[8][8];
    #pragma unroll
    for (int i = 0; i < 8; i++)
        #pragma unroll
        for (int j = 0; j < 8; j++) acc[i][j] = 0.f;

    const float* Ap = A + (size_t)(bm + tid) * K;
    const int idx0 = tid * 2, idx1 = tid * 2 + 1;
    const int br0 = idx0 >> 4, bc0 = (idx0 & 15) * 4;
    const int br1 = idx1 >> 4, bc1 = (idx1 & 15) * 4;

    for (int k0 = 0; k0 < K; k0 += 16) {
        float4 a0 = *(const float4*)(Ap + k0);
        float4 a1 = *(const float4*)(Ap + k0 + 4);
        float4 a2 = *(const float4*)(Ap + k0 + 8);
        float4 a3 = *(const float4*)(Ap + k0 + 12);
        float4 b0 = *(const float4*)(Bw + (size_t)(k0 + br0) * N + bn + bc0);
        float4 b1 = *(const float4*)(Bw + (size_t)(k0 + br1) * N + bn + bc1);
        __syncthreads();
        As[0][tid] = a0.x;  As[1][tid] = a0.y;  As[2][tid] = a0.z;  As[3][tid] = a0.w;
        As[4][tid] = a1.x;  As[5][tid] = a1.y;  As[6][tid] = a1.z;  As[7][tid] = a1.w;
        As[8][tid] = a2.x;  As[9][tid] = a2.y;  As[10][tid] = a2.z; As[11][tid] = a2.w;
        As[12][tid] = a3.x; As[13][tid] = a3.y; As[14][tid] = a3.z; As[15][tid] = a3.w;
        *(float4*)&Bs[br0][bc0] = b0;
        *(float4*)&Bs[br1][bc1] = b1;
        __syncthreads();
        #pragma unroll
        for (int k = 0; k < 16; k++) {
            float av[8], bv[8];
            *(float4*)(av)     = *(const float4*)&As[k][ty * 8];
            *(float4*)(av + 4) = *(const float4*)&As[k][ty * 8 + 4];
            *(float4*)(bv)     = *(const float4*)&Bs[k][tx * 8];
            *(float4*)(bv + 4) = *(const float4*)&Bs[k][tx * 8 + 4];
            #pragma unroll
            for (int i = 0; i < 8; i++)
                #pragma unroll
                for (int j = 0; j < 8; j++) acc[i][j] += av[i] * bv[j];
        }
    }

    #pragma unroll
    for (int i = 0; i < 8; i++) {
        int row = bm + ty * 8 + i;
        int orow = row;
        if (EPI == 2) orow = token_of_winrow(row, roll);
        #pragma unroll
        for (int j = 0; j < 8; j++) {
            int col = bn + tx * 8 + j;
            float v = acc[i][j] + bias[col];
            if (EPI == 1) v = 0.5f * v * (1.f + erff(v * 0.70710678118654752f));
            if (EPI == 2 || EPI == 3) {
                size_t o = (size_t)orow * 192 + col;
                C[o] = res[o] + v;
            } else {
                C[(size_t)row * N + col] = v;
            }
        }
    }
}

// ---------------- attention: one block per (window, head) ----------------
// smem: Q(144x33) K(144x33) S(144x145) biasRow(3312) = 134784 bytes
#define ATTN_SMEM_BYTES ((144*33*2 + 144*145 + 3312) * 4)

__global__ void __launch_bounds__(256)
attn_kernel(const float* __restrict__ qkv, const float* __restrict__ tabT,
            const int* __restrict__ posi, const float* __restrict__ mask,
            float* __restrict__ obuf, int roll)
{
    extern __shared__ float sm[];
    float* Qs = sm;                   // 144*33 (also reused for V)
    float* Ks = Qs + 144 * 33;        // 144*33
    float* Ss = Ks + 144 * 33;        // 144*145
    float* Bt = Ss + 144 * 145;       // 3312

    const int tid = threadIdx.x;
    const int win = blockIdx.x / 6, head = blockIdx.x % 6;

    // bias row for this (win_type, head): win_type = win % 64 (reference reshape semantics)
    const float* trow = tabT + (size_t)((win & 63) * 6 + head) * NPOS;
    for (int i = tid; i < NPOS; i += 256) Bt[i] = trow[i];

    const float* qb = qkv + (size_t)win * (144 * 576) + head * 32;
    for (int e = tid; e < 4608; e += 256) {
        int i = e >> 5, d = e & 31;
        Qs[i * 33 + d] = qb[i * 576 + d] * SCALE_Q;
        Ks[i * 33 + d] = qb[i * 576 + 192 + d];
    }
    __syncthreads();

    // ---- S = Q K^T + bias (+ mask) ; 16x16 thread grid, 9x9 register tile ----
    {
        const int ty = tid >> 4, tx = tid & 15;
        const int i0 = ty * 9, j0 = tx * 9;
        float acc[9][9];
        #pragma unroll
        for (int a = 0; a < 9; a++)
            #pragma unroll
            for (int b = 0; b < 9; b++) acc[a][b] = 0.f;
        #pragma unroll 4
        for (int d = 0; d < 32; d++) {
            float qa[9], kb[9];
            #pragma unroll
            for (int u = 0; u < 9; u++) qa[u] = Qs[(i0 + u) * 33 + d];
            #pragma unroll
            for (int u = 0; u < 9; u++) kb[u] = Ks[(j0 + u) * 33 + d];
            #pragma unroll
            for (int a = 0; a < 9; a++)
                #pragma unroll
                for (int b = 0; b < 9; b++) acc[a][b] += qa[a] * kb[b];
        }
        const float* mwin = mask + (size_t)win * (144 * 144);
        #pragma unroll
        for (int a = 0; a < 9; a++) {
            #pragma unroll
            for (int b = 0; b < 9; b++) {
                int e = (i0 + a) * 144 + (j0 + b);
                float v = acc[a][b] + Bt[posi[e]];
                if (roll) v += mwin[e];
                Ss[(i0 + a) * 145 + (j0 + b)] = v;
            }
        }
    }
    __syncthreads();

    // ---- load V into Qs (Q dead) ; softmax rows in parallel ----
    for (int e = tid; e < 4608; e += 256) {
        int i = e >> 5, d = e & 31;
        Qs[i * 33 + d] = qb[i * 576 + 384 + d];
    }
    {
        const int warp = tid >> 5, lane = tid & 31;
        for (int k = 0; k < 18; k++) {
            int r = warp * 18 + k;
            float* row = Ss + r * 145;
            float m = -1e30f;
            for (int c = lane; c < 144; c += 32) m = fmaxf(m, row[c]);
            #pragma unroll
            for (int o = 16; o; o >>= 1) m = fmaxf(m, __shfl_xor_sync(0xffffffffu, m, o));
            float s = 0.f;
            for (int c = lane; c < 144; c += 32) { float ev = __expf(row[c] - m); row[c] = ev; s += ev; }
            #pragma unroll
            for (int o = 16; o; o >>= 1) s += __shfl_xor_sync(0xffffffffu, s, o);
            float inv = 1.f / s;
            for (int c = lane; c < 144; c += 32) row[c] *= inv;
        }
    }
    __syncthreads();

    // ---- O = S @ V ; 128 threads, 9 rows x 4 cols per thread ----
    if (tid < 128) {
        const int ty = tid >> 3, tx = tid & 7;    // ty 0..15, tx 0..7
        const int i0 = ty * 9, d0 = tx * 4;
        float acc[9][4];
        #pragma unroll
        for (int a = 0; a < 9; a++) { acc[a][0] = acc[a][1] = acc[a][2] = acc[a][3] = 0.f; }
        for (int j = 0; j < 144; j++) {
            float v0 = Qs[j * 33 + d0];
            float v1 = Qs[j * 33 + d0 + 1];
            float v2 = Qs[j * 33 + d0 + 2];
            float v3 = Qs[j * 33 + d0 + 3];
            #pragma unroll
            for (int a = 0; a < 9; a++) {
                float sv = Ss[(i0 + a) * 145 + j];
                acc[a][0] += sv * v0; acc[a][1] += sv * v1;
                acc[a][2] += sv * v2; acc[a][3] += sv * v3;
            }
        }
        float* ob = obuf + (size_t)win * (144 * 192) + head * 32;
        #pragma unroll
        for (int a = 0; a < 9; a++) {
            float4 v = make_float4(acc[a][0], acc[a][1], acc[a][2], acc[a][3]);
            *(float4*)(ob + (size_t)(i0 + a) * 192 + d0) = v;
        }
    }
}

// ---------------- orchestration ----------------
extern "C" void kernel_launch(void* const* d_in, const int* in_sizes, int n_in,
                              void* d_out, int out_size)
{
    const float* x        = (const float*)d_in[0];
    const float* qkv_w    = (const float*)d_in[1];
    const float* qkv_b    = (const float*)d_in[2];
    const float* proj_w   = (const float*)d_in[3];
    const float* proj_b   = (const float*)d_in[4];
    const float* bias_tab = (const float*)d_in[5];
    const float* n1_g     = (const float*)d_in[6];
    const float* n1_b     = (const float*)d_in[7];
    const float* n2_g     = (const float*)d_in[8];
    const float* n2_b     = (const float*)d_in[9];
    const float* mlp_w1   = (const float*)d_in[10];
    const float* mlp_b1   = (const float*)d_in[11];
    const float* mlp_w2   = (const float*)d_in[12];
    const float* mlp_b2   = (const float*)d_in[13];
    const int*   pos_idx  = (const int*)d_in[14];
    const float* attn_mask= (const float*)d_in[15];
    float* out = (float*)d_out;

    float *buf192, *qkvb, *mlp1b, *xA, *xB, *tabT;
    cudaGetSymbolAddress((void**)&buf192, g_buf192);
    cudaGetSymbolAddress((void**)&qkvb,   g_qkv);
    cudaGetSymbolAddress((void**)&mlp1b,  g_mlp1);
    cudaGetSymbolAddress((void**)&xA,     g_xA);
    cudaGetSymbolAddress((void**)&xB,     g_xB);
    cudaGetSymbolAddress((void**)&tabT,   g_tabT);

    cudaFuncSetAttribute(attn_kernel, cudaFuncAttributeMaxDynamicSharedMemorySize,
                         ATTN_SMEM_BYTES);

    {
        const int total = 2 * WTH * NPOS;
        bias_transpose_kernel<<<(total + 255) / 256, 256>>>(bias_tab, tabT);
    }

    for (int blk = 0; blk < 2; blk++) {
        const int roll = blk;  // block 1 is shifted
        const float* xin  = (blk == 0) ? x  : xA;
        float*       xcur = (blk == 0) ? xA : xB;     // after attention residual
        float*       xnxt = (blk == 0) ? xA : out;    // after MLP residual

        // LN1 fused with window partition (+roll gather)
        ln_kernel<<<TOKENS, 192>>>(xin, n1_g + blk * 192, n1_b + blk * 192,
                                   buf192, 1, roll);

        // QKV: (147456x192) @ (192x576)
        sgemm_kernel<0><<<dim3(576 / 64, TOKENS / 128), 128>>>(
            buf192, qkv_w + (size_t)blk * 192 * 576, qkv_b + blk * 576,
            qkvb, nullptr, 576, 192, 0);

        // windowed attention -> buf192 (window layout, [LW, C])
        attn_kernel<<<NWIN * HEADS, 256, ATTN_SMEM_BYTES>>>(
            qkvb, tabT + (size_t)blk * WTH * NPOS, pos_idx, attn_mask, buf192, roll);

        // proj + inverse-window scatter (+unroll) + residual -> xcur
        sgemm_kernel<2><<<dim3(192 / 64, TOKENS / 128), 128>>>(
            buf192, proj_w + (size_t)blk * 192 * 192, proj_b + blk * 192,
            xcur, xin, 192, 192, roll);

        // LN2 (token layout)
        ln_kernel<<<TOKENS, 192>>>(xcur, n2_g + blk * 192, n2_b + blk * 192,
                                   buf192, 0, 0);

        // MLP1 + exact GELU: (x192) @ (192x768)
        sgemm_kernel<1><<<dim3(768 / 64, TOKENS / 128), 128>>>(
            buf192, mlp_w1 + (size_t)blk * 192 * 768, mlp_b1 + blk * 768,
            mlp1b, nullptr, 768, 192, 0);

        // MLP2 + residual: (x768) @ (768x192) -> xnxt
        sgemm_kernel<3><<<dim3(192 / 64, TOKENS / 128), 128>>>(
            mlp1b, mlp_w2 + (size_t)blk * 768 * 192, mlp_b2 + blk * 192,
            xnxt, xcur, 192, 768, 0);
    }
}

// round 16
// speedup vs baseline: 1.6965x; 1.6965x over previous
#include <cuda_runtime.h>
#include <cuda_bf16.h>
#include <stdint.h>
#include <math.h>

// ---------------- problem constants ----------------
#define CDIM 192
#define HEADS 6
#define LW 144
#define NWIN 1024
#define NPOS 3312
#define WTH 384
#define TOKENS 147456
#define SCALE_Q 0.17677669529663687f

// ---------------- scratch (device globals) ----------------
__device__ float          g_qkv [147456*576];
__device__ __nv_bfloat16  g_mlp1[147456*768];
__device__ __nv_bfloat16  g_act [147456*192];
__device__ float          g_xA  [147456*192];
__device__ float          g_xB  [147456*192];
__device__ float          g_tabT[2*384*3312];
__device__ __nv_bfloat16  g_wT  [2*442368];   // per blk: qkvT@0 projT@110592 mlp1T@147456 mlp2T@294912

#define SWZ(o) ((o) ^ (((o) >> 3) & 0x70))

__device__ __forceinline__ uint32_t smem_u32(const void* p) {
    uint32_t a;
    asm("{ .reg .u64 t; cvta.to.shared.u64 t, %1; cvt.u32.u64 %0, t; }" : "=r"(a) : "l"(p));
    return a;
}

#define LDSM_X4(r, addr)                                                              \
    asm volatile("ldmatrix.sync.aligned.m8n8.x4.shared.b16 {%0,%1,%2,%3}, [%4];"      \
        : "=r"((r)[0]), "=r"((r)[1]), "=r"((r)[2]), "=r"((r)[3]) : "r"(addr))

__device__ __forceinline__ void mma16816(float* d, const uint32_t* a,
                                         uint32_t b0, uint32_t b1) {
    asm volatile(
        "mma.sync.aligned.m16n8k16.row.col.f32.bf16.bf16.f32 "
        "{%0,%1,%2,%3}, {%4,%5,%6,%7}, {%8,%9}, {%0,%1,%2,%3};"
        : "+f"(d[0]), "+f"(d[1]), "+f"(d[2]), "+f"(d[3])
        : "r"(a[0]), "r"(a[1]), "r"(a[2]), "r"(a[3]), "r"(b0), "r"(b1));
}

// ---------------- window <-> token index mapping ----------------
__device__ __forceinline__ int token_of_winrow(int r, int roll) {
    int win = r / 144, l = r - win * 144;
    int nz = win >> 8;
    int rem = win & 255;
    int nh = rem >> 4, nw = rem & 15;
    int lz = l / 72; int lr = l - lz * 72;
    int lh = lr / 12; int lw = lr - lh * 12;
    int z = nz * 2 + lz, h = nh * 6 + lh, w = nw * 12 + lw;
    if (roll) {
        z = (z + 1) & 7;
        h += 3; if (h >= 96) h -= 96;
        w += 6; if (w >= 192) w -= 192;
    }
    return (z * 96 + h) * 192 + w;
}

// ---------------- LayerNorm -> bf16 (optional window-permutation gather) ----------------
__global__ void ln_kernel(const float* __restrict__ x, const float* __restrict__ g,
                          const float* __restrict__ b, __nv_bfloat16* __restrict__ out,
                          int gather, int roll)
{
    int r = blockIdx.x;
    int c = threadIdx.x;
    int n = gather ? token_of_winrow(r, roll) : r;
    float v = x[(size_t)n * 192 + c];

    __shared__ float ssum[6], ssq[6];
    float s = v, q = v * v;
    #pragma unroll
    for (int o = 16; o; o >>= 1) {
        s += __shfl_xor_sync(0xffffffffu, s, o);
        q += __shfl_xor_sync(0xffffffffu, q, o);
    }
    int w = c >> 5, l = c & 31;
    if (l == 0) { ssum[w] = s; ssq[w] = q; }
    __syncthreads();
    float ts = 0.f, tq = 0.f;
    #pragma unroll
    for (int i = 0; i < 6; i++) { ts += ssum[i]; tq += ssq[i]; }
    float mean = ts * (1.f / 192.f);
    float var  = tq * (1.f / 192.f) - mean * mean;
    float inv  = rsqrtf(var + 1e-5f);
    out[(size_t)r * 192 + c] = __float2bfloat16((v - mean) * inv * g[c] + b[c]);
}

// ---------------- bias table transpose ----------------
__global__ void bias_transpose_kernel(const float* __restrict__ tab, float* __restrict__ out)
{
    int idx = blockIdx.x * 256 + threadIdx.x;
    const int total = 2 * WTH * NPOS;
    if (idx >= total) return;
    int p = idx % NPOS;
    int rest = idx / NPOS;
    int wth = rest % WTH;
    int blk = rest / WTH;
    out[idx] = tab[((size_t)blk * NPOS + p) * WTH + wth];
}

// ---------------- weight transpose+convert: [K,N] fp32 -> [N,K] bf16 ----------------
__global__ void wprep_kernel(const float* __restrict__ w, __nv_bfloat16* __restrict__ o,
                             int K, int N)
{
    int idx = blockIdx.x * 256 + threadIdx.x;
    if (idx >= N * K) return;
    int n = idx / K, k = idx - n * K;
    o[idx] = __float2bfloat16(w[(size_t)k * N + n]);
}

// ---------------- tensor-core GEMM via mma.sync (bf16 in, fp32 acc) ----------------
// C(M x Nfull) = A(M x Kfull, bf16 row-major) @ BT^T (BT is [Nfull, Kfull] bf16) + bias
// CTA tile 128 x 96, 8 warps (4m x 2n), warp tile 32 x 48, K chunk 192.
// EPI 0: +bias -> fp32 (qkv)
// EPI 1: +bias, GELU -> bf16 (mlp1)
// EPI 2: +bias, window-scatter residual -> fp32 (proj, Nfull==192)
// EPI 3: +bias, same-row residual -> fp32 (mlp2, Nfull==192)
#define GEMM_SMEM_BYTES (1024 + 128*384 + 96*384)

template<int EPI>
__global__ void __launch_bounds__(256)
mma_gemm(const __nv_bfloat16* __restrict__ A, const __nv_bfloat16* __restrict__ BT,
         const float* __restrict__ bias, void* __restrict__ Cout,
         const float* __restrict__ res, int Nfull, int Kfull, int roll)
{
    extern __shared__ char dsm[];
    uint32_t raw = smem_u32(dsm);
    uint32_t base = (raw + 1023) & ~1023u;
    char* sA = dsm + (base - raw);          // 128 rows x 384B
    char* sB = sA + 128 * 384;              // 96 rows x 384B
    const uint32_t uA = base, uB = base + 128 * 384;

    const int tid = threadIdx.x;
    const int bm = blockIdx.y * 128;
    const int bn = blockIdx.x * 96;
    const int warp = tid >> 5, lane = tid & 31;
    const int wm = warp >> 1, wn = warp & 1;

    float acc[2][6][4];
    #pragma unroll
    for (int i = 0; i < 2; i++)
        #pragma unroll
        for (int j = 0; j < 6; j++)
            #pragma unroll
            for (int q = 0; q < 4; q++) acc[i][j][q] = 0.f;

    // precomputed ldmatrix lane addressing
    const int a_row = ((lane >> 3) & 1) * 8 + (lane & 7);
    const int a_kof = (lane >> 4) * 8;
    const int b_row = ((lane >> 4) & 1) * 8 + (lane & 7);
    const int b_kof = ((lane >> 3) & 1) * 8;

    for (int kc = 0; kc < Kfull; kc += 192) {
        // ---- load A tile: 128 rows x 192 bf16 (2 threads/row, 12 uint4 each) ----
        {
            int row = tid >> 1, half = tid & 1;
            const uint4* src = (const uint4*)(A + (size_t)(bm + row) * Kfull + kc + half * 96);
            int ofs = row * 384 + half * 192;
            #pragma unroll
            for (int i = 0; i < 12; i++)
                *(uint4*)(sA + SWZ(ofs + i * 16)) = src[i];
        }
        // ---- load B tile: 96 rows x 192 bf16 ----
        if (tid < 192) {
            int row = tid >> 1, half = tid & 1;
            const uint4* src = (const uint4*)(BT + (size_t)(bn + row) * Kfull + kc + half * 96);
            int ofs = row * 384 + half * 192;
            #pragma unroll
            for (int i = 0; i < 12; i++)
                *(uint4*)(sB + SWZ(ofs + i * 16)) = src[i];
        }
        __syncthreads();

        #pragma unroll
        for (int ks = 0; ks < 12; ks++) {
            uint32_t af[2][4];
            #pragma unroll
            for (int mi = 0; mi < 2; mi++) {
                int r = wm * 32 + mi * 16 + a_row;
                int k = ks * 16 + a_kof;
                LDSM_X4(af[mi], uA + SWZ(r * 384 + k * 2));
            }
            uint32_t bfr[3][4];
            #pragma unroll
            for (int nj = 0; nj < 3; nj++) {
                int n = wn * 48 + nj * 16 + b_row;
                int k = ks * 16 + b_kof;
                LDSM_X4(bfr[nj], uB + SWZ(n * 384 + k * 2));
            }
            #pragma unroll
            for (int mi = 0; mi < 2; mi++)
                #pragma unroll
                for (int nj = 0; nj < 3; nj++) {
                    mma16816(acc[mi][2 * nj],     af[mi], bfr[nj][0], bfr[nj][1]);
                    mma16816(acc[mi][2 * nj + 1], af[mi], bfr[nj][2], bfr[nj][3]);
                }
        }
        __syncthreads();
    }

    // ---- epilogue ----
    const int rofs = lane >> 2;          // 0..7
    const int qcol = (lane & 3) * 2;
    #pragma unroll
    for (int mi = 0; mi < 2; mi++) {
        int r0 = bm + wm * 32 + mi * 16 + rofs;
        int rows[2] = { r0, r0 + 8 };
        int orows[2];
        #pragma unroll
        for (int h = 0; h < 2; h++)
            orows[h] = (EPI == 2) ? token_of_winrow(rows[h], roll) : rows[h];
        #pragma unroll
        for (int nj = 0; nj < 6; nj++) {
            int col = bn + wn * 48 + nj * 8 + qcol;
            float b0 = bias[col], b1 = bias[col + 1];
            #pragma unroll
            for (int h = 0; h < 2; h++) {
                float v0 = acc[mi][nj][2 * h]     + b0;
                float v1 = acc[mi][nj][2 * h + 1] + b1;
                if (EPI == 0) {
                    float* o = (float*)Cout + (size_t)rows[h] * Nfull + col;
                    *(float2*)o = make_float2(v0, v1);
                } else if (EPI == 1) {
                    v0 = 0.5f * v0 * (1.f + erff(v0 * 0.70710678118654752f));
                    v1 = 0.5f * v1 * (1.f + erff(v1 * 0.70710678118654752f));
                    __nv_bfloat16* o = (__nv_bfloat16*)Cout + (size_t)rows[h] * Nfull + col;
                    *(__nv_bfloat162*)o = __floats2bfloat162_rn(v0, v1);
                } else {
                    float* o = (float*)Cout + (size_t)orows[h] * 192 + col;
                    const float* rs = res + (size_t)orows[h] * 192 + col;
                    float2 rv = *(const float2*)rs;
                    *(float2*)o = make_float2(rv.x + v0, rv.y + v1);
                }
            }
        }
    }
}

// ---------------- attention: one block per (window, head) ----------------
#define ATTN_SMEM_BYTES ((144*33*2 + 144*145 + 3312) * 4)

__global__ void __launch_bounds__(256)
attn_kernel(const float* __restrict__ qkv, const float* __restrict__ tabT,
            const int* __restrict__ posi, const float* __restrict__ mask,
            __nv_bfloat16* __restrict__ obuf, int roll)
{
    extern __shared__ float sm[];
    float* Qs = sm;
    float* Ks = Qs + 144 * 33;
    float* Ss = Ks + 144 * 33;
    float* Bt = Ss + 144 * 145;

    const int tid = threadIdx.x;
    const int win = blockIdx.x / 6, head = blockIdx.x % 6;

    const float* trow = tabT + (size_t)((win & 63) * 6 + head) * NPOS;
    for (int i = tid; i < NPOS; i += 256) Bt[i] = trow[i];

    const float* qb = qkv + (size_t)win * (144 * 576) + head * 32;
    for (int e = tid; e < 4608; e += 256) {
        int i = e >> 5, d = e & 31;
        Qs[i * 33 + d] = qb[i * 576 + d] * SCALE_Q;
        Ks[i * 33 + d] = qb[i * 576 + 192 + d];
    }
    __syncthreads();

    {
        const int ty = tid >> 4, tx = tid & 15;
        const int i0 = ty * 9, j0 = tx * 9;
        float acc[9][9];
        #pragma unroll
        for (int a = 0; a < 9; a++)
            #pragma unroll
            for (int b = 0; b < 9; b++) acc[a][b] = 0.f;
        #pragma unroll 4
        for (int d = 0; d < 32; d++) {
            float qa[9], kb[9];
            #pragma unroll
            for (int u = 0; u < 9; u++) qa[u] = Qs[(i0 + u) * 33 + d];
            #pragma unroll
            for (int u = 0; u < 9; u++) kb[u] = Ks[(j0 + u) * 33 + d];
            #pragma unroll
            for (int a = 0; a < 9; a++)
                #pragma unroll
                for (int b = 0; b < 9; b++) acc[a][b] += qa[a] * kb[b];
        }
        const float* mwin = mask + (size_t)win * (144 * 144);
        #pragma unroll
        for (int a = 0; a < 9; a++) {
            #pragma unroll
            for (int b = 0; b < 9; b++) {
                int e = (i0 + a) * 144 + (j0 + b);
                float v = acc[a][b] + Bt[posi[e]];
                if (roll) v += mwin[e];
                Ss[(i0 + a) * 145 + (j0 + b)] = v;
            }
        }
    }
    __syncthreads();

    for (int e = tid; e < 4608; e += 256) {
        int i = e >> 5, d = e & 31;
        Qs[i * 33 + d] = qb[i * 576 + 384 + d];
    }
    {
        const int warp = tid >> 5, lane = tid & 31;
        for (int k = 0; k < 18; k++) {
            int r = warp * 18 + k;
            float* row = Ss + r * 145;
            float m = -1e30f;
            for (int c = lane; c < 144; c += 32) m = fmaxf(m, row[c]);
            #pragma unroll
            for (int o = 16; o; o >>= 1) m = fmaxf(m, __shfl_xor_sync(0xffffffffu, m, o));
            float s = 0.f;
            for (int c = lane; c < 144; c += 32) { float ev = __expf(row[c] - m); row[c] = ev; s += ev; }
            #pragma unroll
            for (int o = 16; o; o >>= 1) s += __shfl_xor_sync(0xffffffffu, s, o);
            float inv = 1.f / s;
            for (int c = lane; c < 144; c += 32) row[c] *= inv;
        }
    }
    __syncthreads();

    if (tid < 128) {
        const int ty = tid >> 3, tx = tid & 7;
        const int i0 = ty * 9, d0 = tx * 4;
        float acc[9][4];
        #pragma unroll
        for (int a = 0; a < 9; a++) { acc[a][0] = acc[a][1] = acc[a][2] = acc[a][3] = 0.f; }
        for (int j = 0; j < 144; j++) {
            float v0 = Qs[j * 33 + d0];
            float v1 = Qs[j * 33 + d0 + 1];
            float v2 = Qs[j * 33 + d0 + 2];
            float v3 = Qs[j * 33 + d0 + 3];
            #pragma unroll
            for (int a = 0; a < 9; a++) {
                float sv = Ss[(i0 + a) * 145 + j];
                acc[a][0] += sv * v0; acc[a][1] += sv * v1;
                acc[a][2] += sv * v2; acc[a][3] += sv * v3;
            }
        }
        __nv_bfloat16* ob = obuf + (size_t)win * (144 * 192) + head * 32;
        #pragma unroll
        for (int a = 0; a < 9; a++) {
            __nv_bfloat162 h0 = __floats2bfloat162_rn(acc[a][0], acc[a][1]);
            __nv_bfloat162 h1 = __floats2bfloat162_rn(acc[a][2], acc[a][3]);
            uint2 u = make_uint2(*(uint32_t*)&h0, *(uint32_t*)&h1);
            *(uint2*)(ob + (size_t)(i0 + a) * 192 + d0) = u;
        }
    }
}

// ---------------- orchestration ----------------
extern "C" void kernel_launch(void* const* d_in, const int* in_sizes, int n_in,
                              void* d_out, int out_size)
{
    const float* x        = (const float*)d_in[0];
    const float* qkv_w    = (const float*)d_in[1];
    const float* qkv_b    = (const float*)d_in[2];
    const float* proj_w   = (const float*)d_in[3];
    const float* proj_b   = (const float*)d_in[4];
    const float* bias_tab = (const float*)d_in[5];
    const float* n1_g     = (const float*)d_in[6];
    const float* n1_b     = (const float*)d_in[7];
    const float* n2_g     = (const float*)d_in[8];
    const float* n2_b     = (const float*)d_in[9];
    const float* mlp_w1   = (const float*)d_in[10];
    const float* mlp_b1   = (const float*)d_in[11];
    const float* mlp_w2   = (const float*)d_in[12];
    const float* mlp_b2   = (const float*)d_in[13];
    const int*   pos_idx  = (const int*)d_in[14];
    const float* attn_mask= (const float*)d_in[15];
    float* out = (float*)d_out;

    float *qkvb, *xA, *xB, *tabT;
    __nv_bfloat16 *mlp1b, *act, *wT;
    cudaGetSymbolAddress((void**)&qkvb,  g_qkv);
    cudaGetSymbolAddress((void**)&mlp1b, g_mlp1);
    cudaGetSymbolAddress((void**)&act,   g_act);
    cudaGetSymbolAddress((void**)&xA,    g_xA);
    cudaGetSymbolAddress((void**)&xB,    g_xB);
    cudaGetSymbolAddress((void**)&tabT,  g_tabT);
    cudaGetSymbolAddress((void**)&wT,    g_wT);

    cudaFuncSetAttribute(attn_kernel, cudaFuncAttributeMaxDynamicSharedMemorySize, ATTN_SMEM_BYTES);
    cudaFuncSetAttribute(mma_gemm<0>, cudaFuncAttributeMaxDynamicSharedMemorySize, GEMM_SMEM_BYTES);
    cudaFuncSetAttribute(mma_gemm<1>, cudaFuncAttributeMaxDynamicSharedMemorySize, GEMM_SMEM_BYTES);
    cudaFuncSetAttribute(mma_gemm<2>, cudaFuncAttributeMaxDynamicSharedMemorySize, GEMM_SMEM_BYTES);
    cudaFuncSetAttribute(mma_gemm<3>, cudaFuncAttributeMaxDynamicSharedMemorySize, GEMM_SMEM_BYTES);

    {
        const int total = 2 * WTH * NPOS;
        bias_transpose_kernel<<<(total + 255) / 256, 256>>>(bias_tab, tabT);
    }
    for (int blk = 0; blk < 2; blk++) {
        __nv_bfloat16* w0 = wT + (size_t)blk * 442368;
        wprep_kernel<<<(110592 + 255) / 256, 256>>>(qkv_w  + (size_t)blk * 192 * 576, w0,          192, 576);
        wprep_kernel<<<(36864  + 255) / 256, 256>>>(proj_w + (size_t)blk * 192 * 192, w0 + 110592, 192, 192);
        wprep_kernel<<<(147456 + 255) / 256, 256>>>(mlp_w1 + (size_t)blk * 192 * 768, w0 + 147456, 192, 768);
        wprep_kernel<<<(147456 + 255) / 256, 256>>>(mlp_w2 + (size_t)blk * 768 * 192, w0 + 294912, 768, 192);
    }

    const int MT = TOKENS / 128;   // 1152
    for (int blk = 0; blk < 2; blk++) {
        const int roll = blk;
        const float* xin  = (blk == 0) ? x  : xA;
        float*       xcur = (blk == 0) ? xA : xB;
        float*       xnxt = (blk == 0) ? xA : out;
        const __nv_bfloat16* w0 = wT + (size_t)blk * 442368;

        ln_kernel<<<TOKENS, 192>>>(xin, n1_g + blk * 192, n1_b + blk * 192, act, 1, roll);

        mma_gemm<0><<<dim3(6, MT), 256, GEMM_SMEM_BYTES>>>(
            act, w0, qkv_b + blk * 576, qkvb, nullptr, 576, 192, 0);

        attn_kernel<<<NWIN * HEADS, 256, ATTN_SMEM_BYTES>>>(
            qkvb, tabT + (size_t)blk * WTH * NPOS, pos_idx, attn_mask, act, roll);

        mma_gemm<2><<<dim3(2, MT), 256, GEMM_SMEM_BYTES>>>(
            act, w0 + 110592, proj_b + blk * 192, xcur, xin, 192, 192, roll);

        ln_kernel<<<TOKENS, 192>>>(xcur, n2_g + blk * 192, n2_b + blk * 192, act, 0, 0);

        mma_gemm<1><<<dim3(8, MT), 256, GEMM_SMEM_BYTES>>>(
            act, w0 + 147456, mlp_b1 + blk * 768, mlp1b, nullptr, 768, 192, 0);

        mma_gemm<3><<<dim3(2, MT), 256, GEMM_SMEM_BYTES>>>(
            mlp1b, w0 + 294912, mlp_b2 + blk * 192, xnxt, xcur, 192, 768, 0);
    }
}